// round 12
// baseline (speedup 1.0000x reference)
#include <cuda_runtime.h>
#include <cuda_bf16.h>
#include <cstdint>

#define B_DIM 16
#define M_DIM 2048
#define F_IN  128
#define F_OUT 64
#define ALPHA 0.2f

// ---------------------------------------------------------------------------
// __device__ scratch (allocation-free rule)
// ---------------------------------------------------------------------------
__device__ float g_r  [(size_t)B_DIM * M_DIM];
__device__ float g_E2 [(size_t)B_DIM * M_DIM];
__device__ float g_E2a[(size_t)B_DIM * M_DIM];
// Wh transposed + bf16 2-term split: [B][F_OUT][M]  (hi + lo)
__device__ __nv_bfloat16 g_WhT_h[(size_t)B_DIM * F_OUT * M_DIM];
__device__ __nv_bfloat16 g_WhT_l[(size_t)B_DIM * F_OUT * M_DIM];

// ---------------------------------------------------------------------------
// helpers
// ---------------------------------------------------------------------------
__device__ __forceinline__ uint32_t smem_u32(const void* p) {
    uint32_t a;
    asm("{ .reg .u64 t; cvta.to.shared.u64 t, %1; cvt.u32.u64 %0, t; }"
        : "=r"(a) : "l"(p));
    return a;
}
// pack two f32 -> bf16x2 (lo 16 bits = a, hi 16 bits = b), round-to-nearest
__device__ __forceinline__ uint32_t pack_bf16(float a, float b) {
    uint32_t r;
    asm("cvt.rn.satfinite.bf16x2.f32 %0, %1, %2;" : "=r"(r) : "f"(b), "f"(a));
    return r;
}
__device__ __forceinline__ void ldsm4(uint32_t* r, uint32_t addr) {
    asm volatile("ldmatrix.sync.aligned.m8n8.x4.shared.b16 {%0,%1,%2,%3}, [%4];"
                 : "=r"(r[0]), "=r"(r[1]), "=r"(r[2]), "=r"(r[3]) : "r"(addr));
}
__device__ __forceinline__ void mma_bf16(float* d, const uint32_t* a,
                                         uint32_t b0, uint32_t b1) {
    asm volatile(
        "mma.sync.aligned.m16n8k16.row.col.f32.bf16.bf16.f32 "
        "{%0,%1,%2,%3}, {%4,%5,%6,%7}, {%8,%9}, {%0,%1,%2,%3};"
        : "+f"(d[0]), "+f"(d[1]), "+f"(d[2]), "+f"(d[3])
        : "r"(a[0]), "r"(a[1]), "r"(a[2]), "r"(a[3]), "r"(b0), "r"(b1));
}
__device__ __forceinline__ void cpa16(uint32_t dst, const void* src) {
    asm volatile("cp.async.cg.shared.global [%0], [%1], 16;"
                 :: "r"(dst), "l"(src) : "memory");
}
#define CP_COMMIT() asm volatile("cp.async.commit_group;" ::: "memory")
#define CP_WAIT0()  asm volatile("cp.async.wait_group 0;" ::: "memory")

// ---------------------------------------------------------------------------
// Kernel 1: Wh = h @ W ; f1/f2 dots ; separable-exp precomputes ;
// Wh transposed + rn bf16 split -> g_WhT_h / g_WhT_l.
// 64 rows per 512-thread CTA (256 CTAs), dynamic smem.
// ---------------------------------------------------------------------------
#define WH_WS   0               // 8192 f32 = 32768 B
#define WH_HS   32768           // 64 x 128 f32 = 32768 B
#define WH_WHS  65536           // 64 x 68 f32 = 17408 B
#define WH_SMEM 82944

__global__ __launch_bounds__(512) void k_wh(const float* __restrict__ h,
                                            const float* __restrict__ W,
                                            const float* __restrict__ a) {
    extern __shared__ char wsm[];
    float* Ws  = (float*)(wsm + WH_WS);
    float* hs  = (float*)(wsm + WH_HS);    // [64][128]
    float* whs = (float*)(wsm + WH_WHS);   // [64][68]
    const int tid = threadIdx.x;
    const size_t row0 = (size_t)blockIdx.x * 64;
    const int b_    = (int)(row0 >> 11);
    const int jbase = (int)(row0 & 2047);

    {
        const float4* ws = (const float4*)W;
        float4* wd = (float4*)Ws;
#pragma unroll
        for (int k = 0; k < 4; ++k) wd[tid + 512 * k] = ws[tid + 512 * k];
        const float4* hsrc = (const float4*)(h + row0 * F_IN);
        float4* hdst = (float4*)hs;
#pragma unroll
        for (int k = 0; k < 4; ++k) hdst[tid + 512 * k] = hsrc[tid + 512 * k];
    }
    __syncthreads();

    const int c  = tid & 63;
    const int r0 = tid >> 6;             // rows r0 + 8u, u = 0..7
    float acc[8];
#pragma unroll
    for (int u = 0; u < 8; ++u) acc[u] = 0.f;
#pragma unroll 4
    for (int k = 0; k < F_IN; ++k) {
        const float wv = Ws[k * F_OUT + c];
#pragma unroll
        for (int u = 0; u < 8; ++u)
            acc[u] += hs[(r0 + 8 * u) * F_IN + k] * wv;
    }
#pragma unroll
    for (int u = 0; u < 8; ++u)
        whs[(r0 + 8 * u) * 68 + c] = acc[u];
    __syncthreads();

    // transposed bf16 split store: thread -> col cc = tid>>3, 8 rows at (tid&7)*8
    {
        const int cc = tid >> 3;
        const int rq = tid & 7;
        float x[8];
#pragma unroll
        for (int u = 0; u < 8; ++u) x[u] = whs[(rq * 8 + u) * 68 + cc];
        uint32_t hh[4], ll[4];
#pragma unroll
        for (int q = 0; q < 4; ++q) {
            hh[q] = pack_bf16(x[2 * q], x[2 * q + 1]);
            const float l0 = x[2 * q]     - __uint_as_float(hh[q] << 16);
            const float l1 = x[2 * q + 1] - __uint_as_float(hh[q] & 0xFFFF0000u);
            ll[q] = pack_bf16(l0, l1);
        }
        const size_t idx = ((size_t)b_ * F_OUT + cc) * M_DIM + jbase + rq * 8;
        *(uint4*)(g_WhT_h + idx) = make_uint4(hh[0], hh[1], hh[2], hh[3]);
        *(uint4*)(g_WhT_l + idx) = make_uint4(ll[0], ll[1], ll[2], ll[3]);
    }

    // f1/f2 per row: 128 threads, each one (row, which) dot of length 64
    if (tid < 128) {
        const int row   = tid >> 1;
        const int which = tid & 1;
        float f = 0.f;
#pragma unroll 8
        for (int k = 0; k < F_OUT; ++k)
            f += whs[row * 68 + k] * a[which * F_OUT + k];
        const size_t grow = row0 + row;
        if (which == 0) {
            g_r[grow] = expf((ALPHA - 1.0f) * f);
        } else {
            g_E2[grow]  = expf(f);
            g_E2a[grow] = expf(ALPHA * f);
        }
    }
}

// ---------------------------------------------------------------------------
// Kernel 2: fused masked-softmax + attn@Wh (mma.sync bf16-split) + elu.
// Grid (16,16): 128 rows x batch. 512 threads = 16 warps (4m x 4n, warp tile
// 32x16). occ 2, one wave. SOFTWARE-PIPELINED over 32 j-tiles of 64:
// per iter: issue adj/e2 LDGs + cp.async B for tile t+1 -> MMA(t) covers the
// latency -> compute p(t+1) into alt A buffer -> one barrier, flip buffers.
// ---------------------------------------------------------------------------
#define BI 128
#define BJ 64
#define APITCH 144               // 72 bf16 per row (9 x 16B) -> conflict-free
#define A_BUF_STRIDE 36864       // (A_H + A_L) = 2 x 128 x 144
#define A_HL 18432               // 128 x 144
#define SB_BASE 73728
#define B_BUF_STRIDE 18432       // (B_H + B_L) = 2 x 64 x 144
#define B_HL 9216                // 64 x 144
#define SRS  110592              // 128 f32 r values
#define SLS  111104              // 128 f32 row sums
#define SMEM_TOTAL 111616

__global__ __launch_bounds__(512, 2) void k_gat(const int* __restrict__ adj,
                                                float* __restrict__ out) {
    extern __shared__ char smem[];
    const uint32_t sbase = smem_u32(smem);
    float* rsm = (float*)(smem + SRS);
    float* ls  = (float*)(smem + SLS);

    const int tid  = threadIdx.x;
    const int lane = tid & 31;
    const int w    = tid >> 5;           // warp 0..15
    const int b    = blockIdx.y;
    const int i0   = blockIdx.x * BI;

    const int mwarp = w >> 2;            // m base = mwarp*32
    const int nwarp = w & 3;             // n base = nwarp*16

    if (tid < 128) rsm[tid] = g_r[(size_t)b * M_DIM + i0 + tid];

    // ldmatrix lane address offsets
    const int quad = lane >> 3, lr = lane & 7;
    const uint32_t aoff = (uint32_t)(((quad & 1) * 8 + lr) * APITCH + (quad >> 1) * 16);
    const uint32_t boff = (uint32_t)(((quad >> 1) * 8 + lr) * APITCH + (quad & 1) * 16);

    // B staging indices (cp.async): thread -> (row, 16B chunk)
    const int rowb = tid >> 3;
    const int chb  = tid & 7;

    float acc[2][2][4];
#pragma unroll
    for (int i = 0; i < 2; ++i)
#pragma unroll
        for (int j = 0; j < 2; ++j)
#pragma unroll
            for (int k = 0; k < 4; ++k) acc[i][j][k] = 0.f;
    float psum[8];
#pragma unroll
    for (int i = 0; i < 8; ++i) psum[i] = 0.f;

    const int jb0 = (2 * blockIdx.x + blockIdx.y) & 31;  // per-CTA stagger
    const size_t ebase = (size_t)b * M_DIM;
    __syncthreads();   // rsm visible

    // ---- prologue: tile 0 -> buffer 0 ----
    {
        const int j0 = jb0 * BJ;
        const size_t gidx = ((size_t)b * F_OUT + rowb) * M_DIM + j0 + chb * 8;
        cpa16(sbase + SB_BASE + rowb * APITCH + chb * 16, g_WhT_h + gidx);
        cpa16(sbase + SB_BASE + B_HL + rowb * APITCH + chb * 16, g_WhT_l + gidx);
        CP_COMMIT();
        const float2 e2v  = *(const float2*)(g_E2  + ebase + j0 + lane * 2);
        const float2 e2av = *(const float2*)(g_E2a + ebase + j0 + lane * 2);
        int2 av[8];
#pragma unroll
        for (int rr = 0; rr < 8; ++rr) {
            const int row = w * 8 + rr;
            av[rr] = *(const int2*)(adj + ((size_t)(b * M_DIM + i0 + row)) * M_DIM
                                        + j0 + lane * 2);
        }
#pragma unroll
        for (int rr = 0; rr < 8; ++rr) {
            const int row = w * 8 + rr;
            const float rv = rsm[row];
            float p0 = fmaxf(e2v.x, rv * e2av.x) * __int_as_float(av[rr].x * 0x3F800000);
            float p1 = fmaxf(e2v.y, rv * e2av.y) * __int_as_float(av[rr].y * 0x3F800000);
            psum[rr] += p0 + p1;
            const uint32_t hh = pack_bf16(p0, p1);
            const uint32_t ll = pack_bf16(p0 - __uint_as_float(hh << 16),
                                          p1 - __uint_as_float(hh & 0xFFFF0000u));
            *(uint32_t*)(smem + row * APITCH + lane * 4) = hh;
            *(uint32_t*)(smem + A_HL + row * APITCH + lane * 4) = ll;
        }
        CP_WAIT0();
        __syncthreads();
    }

    // ---- pipelined main loop over 32 tiles ----
#pragma unroll 1
    for (int t = 0; t < 32; ++t) {
        const int cur = t & 1;
        const int nxt = cur ^ 1;
        int2 av[8];
        float2 e2v, e2av;
        int j0n = 0;

        if (t < 31) {
            j0n = ((t + 1 + jb0) & 31) * BJ;
            // issue next-tile loads FIRST (latency hidden under MMA below)
#pragma unroll
            for (int rr = 0; rr < 8; ++rr) {
                const int row = w * 8 + rr;
                av[rr] = *(const int2*)(adj + ((size_t)(b * M_DIM + i0 + row)) * M_DIM
                                            + j0n + lane * 2);
            }
            e2v  = *(const float2*)(g_E2  + ebase + j0n + lane * 2);
            e2av = *(const float2*)(g_E2a + ebase + j0n + lane * 2);
            const uint32_t nb = sbase + SB_BASE + nxt * B_BUF_STRIDE;
            const size_t gidx = ((size_t)b * F_OUT + rowb) * M_DIM + j0n + chb * 8;
            cpa16(nb + rowb * APITCH + chb * 16, g_WhT_h + gidx);
            cpa16(nb + B_HL + rowb * APITCH + chb * 16, g_WhT_l + gidx);
            CP_COMMIT();
        }

        // --- MMA on tile t (4 k-steps, terms hh + hl + lh) ---
        {
            const uint32_t aAh = sbase + cur * A_BUF_STRIDE + (mwarp * 32) * APITCH + aoff;
            const uint32_t aAl = aAh + A_HL;
            const uint32_t aBh = sbase + SB_BASE + cur * B_BUF_STRIDE
                               + (nwarp * 16) * APITCH + boff;
            const uint32_t aBl = aBh + B_HL;
#pragma unroll
            for (int kt = 0; kt < 4; ++kt) {
                const uint32_t ko = kt * 32;
                uint32_t ah0[4], ah1[4], bh[4], bl[4], al0[4], al1[4];
                ldsm4(ah0, aAh + ko);
                ldsm4(ah1, aAh + 16 * APITCH + ko);
                ldsm4(bh,  aBh + ko);
                mma_bf16(acc[0][0], ah0, bh[0], bh[1]);
                mma_bf16(acc[0][1], ah0, bh[2], bh[3]);
                mma_bf16(acc[1][0], ah1, bh[0], bh[1]);
                mma_bf16(acc[1][1], ah1, bh[2], bh[3]);
                ldsm4(bl, aBl + ko);
                mma_bf16(acc[0][0], ah0, bl[0], bl[1]);
                mma_bf16(acc[0][1], ah0, bl[2], bl[3]);
                mma_bf16(acc[1][0], ah1, bl[0], bl[1]);
                mma_bf16(acc[1][1], ah1, bl[2], bl[3]);
                ldsm4(al0, aAl + ko);
                ldsm4(al1, aAl + 16 * APITCH + ko);
                mma_bf16(acc[0][0], al0, bh[0], bh[1]);
                mma_bf16(acc[0][1], al0, bh[2], bh[3]);
                mma_bf16(acc[1][0], al1, bh[0], bh[1]);
                mma_bf16(acc[1][1], al1, bh[2], bh[3]);
            }
        }

        // --- compute p(t+1) into alt A buffer ---
        if (t < 31) {
            const int abase = nxt * A_BUF_STRIDE;
#pragma unroll
            for (int rr = 0; rr < 8; ++rr) {
                const int row = w * 8 + rr;
                const float rv = rsm[row];
                float p0 = fmaxf(e2v.x, rv * e2av.x) * __int_as_float(av[rr].x * 0x3F800000);
                float p1 = fmaxf(e2v.y, rv * e2av.y) * __int_as_float(av[rr].y * 0x3F800000);
                psum[rr] += p0 + p1;
                const uint32_t hh = pack_bf16(p0, p1);
                const uint32_t ll = pack_bf16(p0 - __uint_as_float(hh << 16),
                                              p1 - __uint_as_float(hh & 0xFFFF0000u));
                *(uint32_t*)(smem + abase + row * APITCH + lane * 4) = hh;
                *(uint32_t*)(smem + abase + A_HL + row * APITCH + lane * 4) = ll;
            }
        }
        CP_WAIT0();
        __syncthreads();
    }

    // --- row sums: per-warp reduce (each row owned by exactly one warp) ---
#pragma unroll
    for (int rr = 0; rr < 8; ++rr) {
        float s = psum[rr];
        s += __shfl_xor_sync(0xffffffffu, s, 16);
        s += __shfl_xor_sync(0xffffffffu, s, 8);
        s += __shfl_xor_sync(0xffffffffu, s, 4);
        s += __shfl_xor_sync(0xffffffffu, s, 2);
        s += __shfl_xor_sync(0xffffffffu, s, 1);
        if (lane == 0) ls[w * 8 + rr] = s;
    }
    __syncthreads();

    // --- epilogue: normalize, ELU, store ---
    const size_t obase = ((size_t)b * M_DIM + i0) * F_OUT;
#pragma unroll
    for (int mt = 0; mt < 2; ++mt) {
        const int r0 = mwarp * 32 + mt * 16 + (lane >> 2);
        const float inv0 = 1.0f / ls[r0];
        const float inv1 = 1.0f / ls[r0 + 8];
#pragma unroll
        for (int nt = 0; nt < 2; ++nt) {
            const int col = nwarp * 16 + nt * 8 + 2 * (lane & 3);
            float x0 = acc[mt][nt][0] * inv0;
            float x1 = acc[mt][nt][1] * inv0;
            float x2 = acc[mt][nt][2] * inv1;
            float x3 = acc[mt][nt][3] * inv1;
            x0 = (x0 > 0.f) ? x0 : (expf(x0) - 1.f);
            x1 = (x1 > 0.f) ? x1 : (expf(x1) - 1.f);
            x2 = (x2 > 0.f) ? x2 : (expf(x2) - 1.f);
            x3 = (x3 > 0.f) ? x3 : (expf(x3) - 1.f);
            *(float2*)(out + obase + (size_t)r0 * F_OUT + col) = make_float2(x0, x1);
            *(float2*)(out + obase + (size_t)(r0 + 8) * F_OUT + col) = make_float2(x2, x3);
        }
    }
}

// ---------------------------------------------------------------------------
extern "C" void kernel_launch(void* const* d_in, const int* in_sizes, int n_in,
                              void* d_out, int out_size) {
    const float* h   = (const float*)d_in[0];
    const int*   adj = (const int*)d_in[1];
    const float* W   = (const float*)d_in[2];
    const float* a   = (const float*)d_in[3];
    float* out = (float*)d_out;
    (void)in_sizes; (void)n_in; (void)out_size;

    cudaFuncSetAttribute(k_wh, cudaFuncAttributeMaxDynamicSharedMemorySize,
                         WH_SMEM);
    cudaFuncSetAttribute(k_gat, cudaFuncAttributeMaxDynamicSharedMemorySize,
                         SMEM_TOTAL);

    k_wh<<<(B_DIM * M_DIM) / 64, 512, WH_SMEM>>>(h, W, a);

    dim3 grid2(M_DIM / BI, B_DIM);
    k_gat<<<grid2, 512, SMEM_TOTAL>>>(adj, out);
}

// round 13
// speedup vs baseline: 1.0702x; 1.0702x over previous
#include <cuda_runtime.h>
#include <cuda_bf16.h>
#include <cstdint>

#define B_DIM 16
#define M_DIM 2048
#define F_IN  128
#define F_OUT 64
#define ALPHA 0.2f

// ---------------------------------------------------------------------------
// __device__ scratch (allocation-free rule)
// ---------------------------------------------------------------------------
__device__ float g_r  [(size_t)B_DIM * M_DIM];
__device__ float g_E2 [(size_t)B_DIM * M_DIM];
__device__ float g_E2a[(size_t)B_DIM * M_DIM];
// Wh transposed + bf16 2-term split: [B][F_OUT][M]  (hi + lo)
__device__ __nv_bfloat16 g_WhT_h[(size_t)B_DIM * F_OUT * M_DIM];
__device__ __nv_bfloat16 g_WhT_l[(size_t)B_DIM * F_OUT * M_DIM];

// ---------------------------------------------------------------------------
// helpers
// ---------------------------------------------------------------------------
__device__ __forceinline__ uint32_t smem_u32(const void* p) {
    uint32_t a;
    asm("{ .reg .u64 t; cvta.to.shared.u64 t, %1; cvt.u32.u64 %0, t; }"
        : "=r"(a) : "l"(p));
    return a;
}
__device__ __forceinline__ uint32_t pack_bf16(float a, float b) {
    uint32_t r;
    asm("cvt.rn.satfinite.bf16x2.f32 %0, %1, %2;" : "=r"(r) : "f"(b), "f"(a));
    return r;
}
__device__ __forceinline__ void ldsm4(uint32_t* r, uint32_t addr) {
    asm volatile("ldmatrix.sync.aligned.m8n8.x4.shared.b16 {%0,%1,%2,%3}, [%4];"
                 : "=r"(r[0]), "=r"(r[1]), "=r"(r[2]), "=r"(r[3]) : "r"(addr));
}
__device__ __forceinline__ void mma_bf16(float* d, const uint32_t* a,
                                         uint32_t b0, uint32_t b1) {
    asm volatile(
        "mma.sync.aligned.m16n8k16.row.col.f32.bf16.bf16.f32 "
        "{%0,%1,%2,%3}, {%4,%5,%6,%7}, {%8,%9}, {%0,%1,%2,%3};"
        : "+f"(d[0]), "+f"(d[1]), "+f"(d[2]), "+f"(d[3])
        : "r"(a[0]), "r"(a[1]), "r"(a[2]), "r"(a[3]), "r"(b0), "r"(b1));
}
__device__ __forceinline__ void cpa16(uint32_t dst, const void* src) {
    asm volatile("cp.async.cg.shared.global [%0], [%1], 16;"
                 :: "r"(dst), "l"(src) : "memory");
}
#define CP_COMMIT() asm volatile("cp.async.commit_group;" ::: "memory")
#define CP_WAIT2()  asm volatile("cp.async.wait_group 2;" ::: "memory")

// ---------------------------------------------------------------------------
// Kernel 1: Wh = h @ W ; f1/f2 dots ; separable-exp precomputes ;
// Wh transposed + rn bf16 split. 64 rows / 512-thr CTA. (unchanged from R11)
// ---------------------------------------------------------------------------
#define WH_WS   0
#define WH_HS   32768
#define WH_WHS  65536
#define WH_SMEM 82944

__global__ __launch_bounds__(512) void k_wh(const float* __restrict__ h,
                                            const float* __restrict__ W,
                                            const float* __restrict__ a) {
    extern __shared__ char wsm[];
    float* Ws  = (float*)(wsm + WH_WS);
    float* hs  = (float*)(wsm + WH_HS);
    float* whs = (float*)(wsm + WH_WHS);
    const int tid = threadIdx.x;
    const size_t row0 = (size_t)blockIdx.x * 64;
    const int b_    = (int)(row0 >> 11);
    const int jbase = (int)(row0 & 2047);

    {
        const float4* ws = (const float4*)W;
        float4* wd = (float4*)Ws;
#pragma unroll
        for (int k = 0; k < 4; ++k) wd[tid + 512 * k] = ws[tid + 512 * k];
        const float4* hsrc = (const float4*)(h + row0 * F_IN);
        float4* hdst = (float4*)hs;
#pragma unroll
        for (int k = 0; k < 4; ++k) hdst[tid + 512 * k] = hsrc[tid + 512 * k];
    }
    __syncthreads();

    const int c  = tid & 63;
    const int r0 = tid >> 6;
    float acc[8];
#pragma unroll
    for (int u = 0; u < 8; ++u) acc[u] = 0.f;
#pragma unroll 4
    for (int k = 0; k < F_IN; ++k) {
        const float wv = Ws[k * F_OUT + c];
#pragma unroll
        for (int u = 0; u < 8; ++u)
            acc[u] += hs[(r0 + 8 * u) * F_IN + k] * wv;
    }
#pragma unroll
    for (int u = 0; u < 8; ++u)
        whs[(r0 + 8 * u) * 68 + c] = acc[u];
    __syncthreads();

    {
        const int cc = tid >> 3;
        const int rq = tid & 7;
        float x[8];
#pragma unroll
        for (int u = 0; u < 8; ++u) x[u] = whs[(rq * 8 + u) * 68 + cc];
        uint32_t hh[4], ll[4];
#pragma unroll
        for (int q = 0; q < 4; ++q) {
            hh[q] = pack_bf16(x[2 * q], x[2 * q + 1]);
            const float l0 = x[2 * q]     - __uint_as_float(hh[q] << 16);
            const float l1 = x[2 * q + 1] - __uint_as_float(hh[q] & 0xFFFF0000u);
            ll[q] = pack_bf16(l0, l1);
        }
        const size_t idx = ((size_t)b_ * F_OUT + cc) * M_DIM + jbase + rq * 8;
        *(uint4*)(g_WhT_h + idx) = make_uint4(hh[0], hh[1], hh[2], hh[3]);
        *(uint4*)(g_WhT_l + idx) = make_uint4(ll[0], ll[1], ll[2], ll[3]);
    }

    if (tid < 128) {
        const int row   = tid >> 1;
        const int which = tid & 1;
        float f = 0.f;
#pragma unroll 8
        for (int k = 0; k < F_OUT; ++k)
            f += whs[row * 68 + k] * a[which * F_OUT + k];
        const size_t grow = row0 + row;
        if (which == 0) {
            g_r[grow] = expf((ALPHA - 1.0f) * f);
        } else {
            g_E2[grow]  = expf(f);
            g_E2a[grow] = expf(ALPHA * f);
        }
    }
}

// ---------------------------------------------------------------------------
// Kernel 2: fused masked-softmax + attn@Wh (mma.sync bf16-split) + elu.
// Grid (16,16): 128 rows x batch. 512 threads = 16 warps (4m x 4n).
// 64 j-tiles of 32. Raw adj streamed through a 3-slot cp.async ring (loads
// never stop for barriers); e2/e2a ringed alongside; B (k=64 pairs)
// double-buffered in the same commit-group FIFO, one group per iter,
// wait_group 2.
// ---------------------------------------------------------------------------
#define BI 128
#define NT 64                    // j tiles of 32
#define APITCH 80                // A row: 32 bf16 = 64B + 16 pad
#define BPITCH 144               // B row: 64 bf16 = 128B + 16 pad
#define SADJ 0                   // 3 x 16384
#define SA_H 49152               // 128 x 80 = 10240
#define SA_L 59392               // 10240
#define SB   69632               // 2 x 18432 (hi 9216 + lo 9216)
#define SE2  106496              // 3 x 256
#define SLS  107264              // 128 f32
#define SMEM_TOTAL 107776

__global__ __launch_bounds__(512, 2) void k_gat(const int* __restrict__ adj,
                                                float* __restrict__ out) {
    extern __shared__ char smem[];
    const uint32_t sbase = smem_u32(smem);
    float* ls = (float*)(smem + SLS);

    const int tid  = threadIdx.x;
    const int lane = tid & 31;
    const int w    = tid >> 5;           // warp 0..15
    const int b    = blockIdx.y;
    const int i0   = blockIdx.x * BI;
    const size_t brow = (size_t)b * M_DIM;
    const size_t ebase = brow;

    const int mwarp = w >> 2;            // m base = mwarp*32
    const int nwarp = w & 3;             // n base = nwarp*16
    const int P = (2 * blockIdx.x + blockIdx.y) & 31;   // tile stagger (pairs)

    // ldmatrix lane offsets
    const int quad = lane >> 3, lr = lane & 7;
    const uint32_t aoff = (uint32_t)(((quad & 1) * 8 + lr) * APITCH + (quad >> 1) * 16);
    const uint32_t boff = (uint32_t)(((quad >> 1) * 8 + lr) * BPITCH + (quad & 1) * 16);
    const uint32_t aAh = sbase + SA_H + (mwarp * 32) * APITCH + aoff;
    const uint32_t aAl = sbase + SA_L + (mwarp * 32) * APITCH + aoff;

    // staging indices
    const int sr  = tid >> 3;            // adj row / B row (0..63 for B)
    const int sch = tid & 7;             // 16B chunk

    // p-compute mapping: per pass, lane -> (row parity, j-pair)
    const int jp = lane & 15;
    const int rh = lane >> 4;

    // r values: 4 regs (row = w*8 + pass*2 + rh)
    float rv4[4];
#pragma unroll
    for (int p = 0; p < 4; ++p)
        rv4[p] = g_r[brow + i0 + w * 8 + p * 2 + rh];

    float acc[2][2][4];
#pragma unroll
    for (int i = 0; i < 2; ++i)
#pragma unroll
        for (int j = 0; j < 2; ++j)
#pragma unroll
            for (int k = 0; k < 4; ++k) acc[i][j][k] = 0.f;
    float psum[4];
#pragma unroll
    for (int p = 0; p < 4; ++p) psum[p] = 0.f;

    // ---- staging lambdas (as macros via inline code) ----
#define STAGE_ADJ(T, SLOT) do {                                               \
        const int j0_ = (((T) + 2 * P) & 63) * 32;                            \
        const uint32_t d_ = sbase + SADJ + (SLOT) * 16384;                    \
        cpa16(d_ + (sr) * 128 + sch * 16,                                     \
              adj + (brow + i0 + sr) * (size_t)M_DIM + j0_ + sch * 4);        \
        cpa16(d_ + (sr + 64) * 128 + sch * 16,                                \
              adj + (brow + i0 + sr + 64) * (size_t)M_DIM + j0_ + sch * 4);   \
    } while (0)
#define STAGE_E2(T, SLOT) do {                                                \
        if (tid < 16) {                                                       \
            const int j0_ = (((T) + 2 * P) & 63) * 32;                        \
            const int half_ = tid >> 3, q_ = tid & 7;                         \
            const float* src_ = (half_ ? g_E2a : g_E2) + ebase + j0_ + q_ * 4;\
            cpa16(sbase + SE2 + (SLOT) * 256 + half_ * 128 + q_ * 16, src_);  \
        }                                                                     \
    } while (0)
#define STAGE_B(S) do {                                                       \
        const int jp0_ = (((S) + P) & 31) * 64;                               \
        const uint32_t d_ = sbase + SB + ((S) & 1) * 18432;                   \
        const size_t g_ = ((size_t)b * F_OUT + sr) * M_DIM + jp0_ + sch * 8;  \
        cpa16(d_ + sr * BPITCH + sch * 16, g_WhT_h + g_);                     \
        cpa16(d_ + 9216 + sr * BPITCH + sch * 16, g_WhT_l + g_);              \
    } while (0)

    // ---- prologue: 2 groups ----
    STAGE_ADJ(0, 0); STAGE_E2(0, 0); STAGE_B(0);
    CP_COMMIT();
    STAGE_ADJ(1, 1); STAGE_E2(1, 1);
    CP_COMMIT();

    // ---- main loop over 64 tiles ----
#pragma unroll 1
    for (int t = 0; t < NT; ++t) {
        // commit group for t+2 (always commit to keep FIFO arithmetic exact)
        if (t + 2 < NT) {
            STAGE_ADJ(t + 2, (t + 2) % 3);
            STAGE_E2(t + 2, (t + 2) % 3);
            if (((t & 1) == 0) && (t / 2 + 1) < 32) STAGE_B(t / 2 + 1);
        }
        CP_COMMIT();
        CP_WAIT2();
        __syncthreads();   // SYNC1: cp.async data visible; A free from MMA(t-1)

        // --- p-compute(t): adj smem -> split bf16 A tiles ---
        {
            const uint32_t adjb = sbase + SADJ + (t % 3) * 16384;
            const uint32_t e2b  = sbase + SE2 + (t % 3) * 256;
            const float2 e2v  = *(const float2*)(smem + (e2b - sbase) + jp * 8);
            const float2 e2av = *(const float2*)(smem + (e2b - sbase) + 128 + jp * 8);
#pragma unroll
            for (int pass = 0; pass < 4; ++pass) {
                const int row = w * 8 + pass * 2 + rh;
                const float rv = rv4[pass];
                const uint2 av = *(const uint2*)(smem + (adjb - sbase)
                                                 + row * 128 + jp * 8);
                float p0 = fmaxf(e2v.x, rv * e2av.x)
                         * __int_as_float((int)av.x * 0x3F800000);
                float p1 = fmaxf(e2v.y, rv * e2av.y)
                         * __int_as_float((int)av.y * 0x3F800000);
                psum[pass] += p0 + p1;
                const uint32_t hh = pack_bf16(p0, p1);
                const uint32_t ll = pack_bf16(p0 - __uint_as_float(hh << 16),
                                              p1 - __uint_as_float(hh & 0xFFFF0000u));
                *(uint32_t*)(smem + SA_H + row * APITCH + jp * 4) = hh;
                *(uint32_t*)(smem + SA_L + row * APITCH + jp * 4) = ll;
            }
        }
        __syncthreads();   // SYNC2: A ready

        // --- MMA(t): 2 k-steps, terms hh + hl + lh ---
        {
            const uint32_t aBh = sbase + SB + ((t >> 1) & 1) * 18432
                               + (nwarp * 16) * BPITCH + boff;
            const uint32_t aBl = aBh + 9216;
            const uint32_t kb  = (t & 1) * 64;   // byte offset of this tile's k in B
#pragma unroll
            for (int ktl = 0; ktl < 2; ++ktl) {
                const uint32_t koA = ktl * 32;
                const uint32_t koB = kb + ktl * 32;
                uint32_t ah0[4], ah1[4], bh[4], bl[4], al0[4], al1[4];
                ldsm4(ah0, aAh + koA);
                ldsm4(ah1, aAh + 16 * APITCH + koA);
                ldsm4(bh,  aBh + koB);
                mma_bf16(acc[0][0], ah0, bh[0], bh[1]);
                mma_bf16(acc[0][1], ah0, bh[2], bh[3]);
                mma_bf16(acc[1][0], ah1, bh[0], bh[1]);
                mma_bf16(acc[1][1], ah1, bh[2], bh[3]);
                ldsm4(bl, aBl + koB);
                mma_bf16(acc[0][0], ah0, bl[0], bl[1]);
                mma_bf16(acc[0][1], ah0, bl[2], bl[3]);
                mma_bf16(acc[1][0], ah1, bl[0], bl[1]);
                mma_bf16(acc[1][1], ah1, bl[2], bl[3]);
                ldsm4(al0, aAl + koA);
                ldsm4(al1, aAl + 16 * APITCH + koA);
                mma_bf16(acc[0][0], al0, bh[0], bh[1]);
                mma_bf16(acc[0][1], al0, bh[2], bh[3]);
                mma_bf16(acc[1][0], al1, bh[0], bh[1]);
                mma_bf16(acc[1][1], al1, bh[2], bh[3]);
            }
        }
    }

    // --- row sums: reduce within 16-lane halves (each half owns a row) ---
#pragma unroll
    for (int pass = 0; pass < 4; ++pass) {
        float s = psum[pass];
        s += __shfl_xor_sync(0xffffffffu, s, 8);
        s += __shfl_xor_sync(0xffffffffu, s, 4);
        s += __shfl_xor_sync(0xffffffffu, s, 2);
        s += __shfl_xor_sync(0xffffffffu, s, 1);
        if ((lane & 15) == 0)
            ls[w * 8 + pass * 2 + rh] = s;
    }
    __syncthreads();

    // --- epilogue: normalize, ELU, store ---
    const size_t obase = (brow + i0) * F_OUT;
#pragma unroll
    for (int mt = 0; mt < 2; ++mt) {
        const int r0 = mwarp * 32 + mt * 16 + (lane >> 2);
        const float inv0 = 1.0f / ls[r0];
        const float inv1 = 1.0f / ls[r0 + 8];
#pragma unroll
        for (int nt = 0; nt < 2; ++nt) {
            const int col = nwarp * 16 + nt * 8 + 2 * (lane & 3);
            float x0 = acc[mt][nt][0] * inv0;
            float x1 = acc[mt][nt][1] * inv0;
            float x2 = acc[mt][nt][2] * inv1;
            float x3 = acc[mt][nt][3] * inv1;
            x0 = (x0 > 0.f) ? x0 : (expf(x0) - 1.f);
            x1 = (x1 > 0.f) ? x1 : (expf(x1) - 1.f);
            x2 = (x2 > 0.f) ? x2 : (expf(x2) - 1.f);
            x3 = (x3 > 0.f) ? x3 : (expf(x3) - 1.f);
            *(float2*)(out + obase + (size_t)r0 * F_OUT + col) = make_float2(x0, x1);
            *(float2*)(out + obase + (size_t)(r0 + 8) * F_OUT + col) = make_float2(x2, x3);
        }
    }
}

// ---------------------------------------------------------------------------
extern "C" void kernel_launch(void* const* d_in, const int* in_sizes, int n_in,
                              void* d_out, int out_size) {
    const float* h   = (const float*)d_in[0];
    const int*   adj = (const int*)d_in[1];
    const float* W   = (const float*)d_in[2];
    const float* a   = (const float*)d_in[3];
    float* out = (float*)d_out;
    (void)in_sizes; (void)n_in; (void)out_size;

    cudaFuncSetAttribute(k_wh, cudaFuncAttributeMaxDynamicSharedMemorySize,
                         WH_SMEM);
    cudaFuncSetAttribute(k_gat, cudaFuncAttributeMaxDynamicSharedMemorySize,
                         SMEM_TOTAL);

    k_wh<<<(B_DIM * M_DIM) / 64, 512, WH_SMEM>>>(h, W, a);

    dim3 grid2(M_DIM / BI, B_DIM);
    k_gat<<<grid2, 512, SMEM_TOTAL>>>(adj, out);
}

// round 15
// speedup vs baseline: 1.2295x; 1.1488x over previous
#include <cuda_runtime.h>
#include <cuda_bf16.h>
#include <cstdint>

#define B_DIM 16
#define M_DIM 2048
#define F_IN  128
#define F_OUT 64
#define ALPHA 0.2f

// ---------------------------------------------------------------------------
// __device__ scratch (allocation-free rule)
// ---------------------------------------------------------------------------
__device__ float g_r  [(size_t)B_DIM * M_DIM];
__device__ float g_E2 [(size_t)B_DIM * M_DIM];
__device__ float g_E2a[(size_t)B_DIM * M_DIM];
// Wh transposed + bf16 2-term split: [B][F_OUT][M]  (hi + lo)
__device__ __nv_bfloat16 g_WhT_h[(size_t)B_DIM * F_OUT * M_DIM];
__device__ __nv_bfloat16 g_WhT_l[(size_t)B_DIM * F_OUT * M_DIM];

// ---------------------------------------------------------------------------
// helpers
// ---------------------------------------------------------------------------
__device__ __forceinline__ uint32_t smem_u32(const void* p) {
    uint32_t a;
    asm("{ .reg .u64 t; cvta.to.shared.u64 t, %1; cvt.u32.u64 %0, t; }"
        : "=r"(a) : "l"(p));
    return a;
}
__device__ __forceinline__ uint32_t pack_bf16(float a, float b) {
    uint32_t r;
    asm("cvt.rn.satfinite.bf16x2.f32 %0, %1, %2;" : "=r"(r) : "f"(b), "f"(a));
    return r;
}
__device__ __forceinline__ void ldsm4(uint32_t* r, uint32_t addr) {
    asm volatile("ldmatrix.sync.aligned.m8n8.x4.shared.b16 {%0,%1,%2,%3}, [%4];"
                 : "=r"(r[0]), "=r"(r[1]), "=r"(r[2]), "=r"(r[3]) : "r"(addr));
}
__device__ __forceinline__ void mma_bf16(float* d, const uint32_t* a,
                                         uint32_t b0, uint32_t b1) {
    asm volatile(
        "mma.sync.aligned.m16n8k16.row.col.f32.bf16.bf16.f32 "
        "{%0,%1,%2,%3}, {%4,%5,%6,%7}, {%8,%9}, {%0,%1,%2,%3};"
        : "+f"(d[0]), "+f"(d[1]), "+f"(d[2]), "+f"(d[3])
        : "r"(a[0]), "r"(a[1]), "r"(a[2]), "r"(a[3]), "r"(b0), "r"(b1));
}
__device__ __forceinline__ void cpa16(uint32_t dst, const void* src) {
    asm volatile("cp.async.cg.shared.global [%0], [%1], 16;"
                 :: "r"(dst), "l"(src) : "memory");
}
#define CP_COMMIT() asm volatile("cp.async.commit_group;" ::: "memory")
#define CP_WAIT2()  asm volatile("cp.async.wait_group 2;" ::: "memory")
// named barriers (producer/consumer handshake), count = all 512 threads
#define BAR_SYNC(id)   asm volatile("bar.sync %0, 512;"   :: "r"(id) : "memory")
#define BAR_ARRIVE(id) asm volatile("bar.arrive %0, 512;" :: "r"(id) : "memory")
#define FULL(s)  (1 + (s))
#define EMPTY(s) (3 + (s))

// ---------------------------------------------------------------------------
// Kernel 1: Wh = h @ W ; f1/f2 dots ; separable-exp precomputes ;
// Wh transposed + rn bf16 split. 64 rows / 512-thr CTA. (unchanged)
// ---------------------------------------------------------------------------
#define WH_WS   0
#define WH_HS   32768
#define WH_WHS  65536
#define WH_SMEM 82944

__global__ __launch_bounds__(512) void k_wh(const float* __restrict__ h,
                                            const float* __restrict__ W,
                                            const float* __restrict__ a) {
    extern __shared__ char wsm[];
    float* Ws  = (float*)(wsm + WH_WS);
    float* hs  = (float*)(wsm + WH_HS);
    float* whs = (float*)(wsm + WH_WHS);
    const int tid = threadIdx.x;
    const size_t row0 = (size_t)blockIdx.x * 64;
    const int b_    = (int)(row0 >> 11);
    const int jbase = (int)(row0 & 2047);

    {
        const float4* ws = (const float4*)W;
        float4* wd = (float4*)Ws;
#pragma unroll
        for (int k = 0; k < 4; ++k) wd[tid + 512 * k] = ws[tid + 512 * k];
        const float4* hsrc = (const float4*)(h + row0 * F_IN);
        float4* hdst = (float4*)hs;
#pragma unroll
        for (int k = 0; k < 4; ++k) hdst[tid + 512 * k] = hsrc[tid + 512 * k];
    }
    __syncthreads();

    const int c  = tid & 63;
    const int r0 = tid >> 6;
    float acc[8];
#pragma unroll
    for (int u = 0; u < 8; ++u) acc[u] = 0.f;
#pragma unroll 4
    for (int k = 0; k < F_IN; ++k) {
        const float wv = Ws[k * F_OUT + c];
#pragma unroll
        for (int u = 0; u < 8; ++u)
            acc[u] += hs[(r0 + 8 * u) * F_IN + k] * wv;
    }
#pragma unroll
    for (int u = 0; u < 8; ++u)
        whs[(r0 + 8 * u) * 68 + c] = acc[u];
    __syncthreads();

    {
        const int cc = tid >> 3;
        const int rq = tid & 7;
        float x[8];
#pragma unroll
        for (int u = 0; u < 8; ++u) x[u] = whs[(rq * 8 + u) * 68 + cc];
        uint32_t hh[4], ll[4];
#pragma unroll
        for (int q = 0; q < 4; ++q) {
            hh[q] = pack_bf16(x[2 * q], x[2 * q + 1]);
            const float l0 = x[2 * q]     - __uint_as_float(hh[q] << 16);
            const float l1 = x[2 * q + 1] - __uint_as_float(hh[q] & 0xFFFF0000u);
            ll[q] = pack_bf16(l0, l1);
        }
        const size_t idx = ((size_t)b_ * F_OUT + cc) * M_DIM + jbase + rq * 8;
        *(uint4*)(g_WhT_h + idx) = make_uint4(hh[0], hh[1], hh[2], hh[3]);
        *(uint4*)(g_WhT_l + idx) = make_uint4(ll[0], ll[1], ll[2], ll[3]);
    }

    if (tid < 128) {
        const int row   = tid >> 1;
        const int which = tid & 1;
        float f = 0.f;
#pragma unroll 8
        for (int k = 0; k < F_OUT; ++k)
            f += whs[row * 68 + k] * a[which * F_OUT + k];
        const size_t grow = row0 + row;
        if (which == 0) {
            g_r[grow] = expf((ALPHA - 1.0f) * f);
        } else {
            g_E2[grow]  = expf(f);
            g_E2a[grow] = expf(ALPHA * f);
        }
    }
}

// ---------------------------------------------------------------------------
// Kernel 2: WARP-SPECIALIZED fused masked-softmax + attn@Wh + elu.
// Grid (16,16): CTA = 128 rows x batch, 512 threads.
// Warps 0-7 PRODUCERS: adj LDG.128 -> p -> split-bf16 A (double buf),
//   B cp.async (TRIPLE buffered, staged on odd tiles AFTER the EMPTY sync
//   that proves the target buffer is free), row sums.
// Warps 8-15 CONSUMERS: LDSM + HMMA (4m x 2n, warp tile m32 x n32).
// One cp.async commit group per producer tile -> CP_WAIT2 at tile t
// guarantees all groups <= t-2 complete (B ready 1 tile early).
// ---------------------------------------------------------------------------
#define BI 128
#define NT 64
#define APITCH 80                // A row: 32 bf16 = 64B + 16 pad
#define BPITCH 144               // B row: 64 bf16 = 128B + 16 pad
#define A_BUF 20480              // hi 10240 + lo 10240
#define A_HL 10240
#define SB   40960               // 3 x 18432 (hi 9216 + lo 9216)
#define B_BUF 18432
#define B_HL 9216
#define SRS  96256               // 128 f32 r values
#define SLS  96768               // 128 f32 row sums
#define SMEM_TOTAL 97280

__global__ __launch_bounds__(512, 2) void k_gat(const int* __restrict__ adj,
                                                float* __restrict__ out) {
    extern __shared__ char smem[];
    const uint32_t sbase = smem_u32(smem);
    float* rsm = (float*)(smem + SRS);
    float* ls  = (float*)(smem + SLS);

    const int tid  = threadIdx.x;
    const int lane = tid & 31;
    const int w    = tid >> 5;           // warp 0..15
    const int b    = blockIdx.y;
    const int i0   = blockIdx.x * BI;
    const size_t brow = (size_t)b * M_DIM;
    const int P = (2 * blockIdx.x + blockIdx.y) & 31;   // stagger (j pairs)

    if (tid < 128) rsm[tid] = g_r[brow + i0 + tid];

#define STAGE_B(S) do {                                                       \
        const int jp0_ = (((S) + P) & 31) * 64;                               \
        const int bsr_ = tid >> 2;                                            \
        const int bc0_ = tid & 3;                                             \
        const size_t gsrc_ = ((size_t)b * F_OUT + bsr_) * M_DIM + jp0_;       \
        const uint32_t d0_ = sbase + SB + ((S) % 3) * B_BUF + bsr_ * BPITCH;  \
        cpa16(d0_ + bc0_ * 16,              g_WhT_h + gsrc_ + bc0_ * 8);      \
        cpa16(d0_ + (bc0_ + 4) * 16,        g_WhT_h + gsrc_ + (bc0_ + 4) * 8);\
        cpa16(d0_ + B_HL + bc0_ * 16,       g_WhT_l + gsrc_ + bc0_ * 8);      \
        cpa16(d0_ + B_HL + (bc0_ + 4) * 16, g_WhT_l + gsrc_ + (bc0_ + 4) * 8);\
    } while (0)

    // ---- prologue: producers stage B(0), B(1) as two groups ----
    if (w < 8) {
        STAGE_B(0);
        CP_COMMIT();
        STAGE_B(1);
        CP_COMMIT();
    }
    __syncthreads();       // rsm visible

    if (w < 8) {
        // ================= PRODUCER =================
        const int pw   = w;
        const int jq   = lane & 7;       // int4 column group
        const int rsub = lane >> 3;      // 0..3
        float psum[4];
#pragma unroll
        for (int p = 0; p < 4; ++p) psum[p] = 0.f;

#pragma unroll 1
        for (int t = 0; t < NT; ++t) {
            const int slot = t & 1;
            const int s = t >> 1;
            const int j0 = ((t + 2 * P) & 63) * 32;

            // issue adj + e2 loads early (latency covered before p-compute)
            int4 av[4];
#pragma unroll
            for (int ps = 0; ps < 4; ++ps) {
                const int row = pw * 16 + ps * 4 + rsub;
                av[ps] = *(const int4*)(adj + (brow + i0 + row) * (size_t)M_DIM
                                            + j0 + jq * 4);
            }
            const float4 e2v  = *(const float4*)(g_E2  + brow + j0 + jq * 4);
            const float4 e2av = *(const float4*)(g_E2a + brow + j0 + jq * 4);

            // A-slot free?  (also proves consumers finished tile t-2, so on
            // odd tiles buffer (s+2)%3 == (s-1)%3 is free for B staging)
            if (t >= 2) BAR_SYNC(EMPTY(slot));

            if ((t & 1) == 1 && (s + 2) < 32) STAGE_B(s + 2);
            CP_COMMIT();      // exactly one group per tile (may be empty)
            CP_WAIT2();       // all groups <= t-2 complete -> current B ready

            const uint32_t abase = sbase + slot * A_BUF;
#pragma unroll
            for (int ps = 0; ps < 4; ++ps) {
                const int row = pw * 16 + ps * 4 + rsub;
                const float rv = rsm[row];
                const int4 a = av[ps];
                float p0 = fmaxf(e2v.x, rv * e2av.x) * __int_as_float(a.x * 0x3F800000);
                float p1 = fmaxf(e2v.y, rv * e2av.y) * __int_as_float(a.y * 0x3F800000);
                float p2 = fmaxf(e2v.z, rv * e2av.z) * __int_as_float(a.z * 0x3F800000);
                float p3 = fmaxf(e2v.w, rv * e2av.w) * __int_as_float(a.w * 0x3F800000);
                psum[ps] += (p0 + p1) + (p2 + p3);
                const uint32_t h01 = pack_bf16(p0, p1);
                const uint32_t h23 = pack_bf16(p2, p3);
                const uint32_t l01 = pack_bf16(p0 - __uint_as_float(h01 << 16),
                                               p1 - __uint_as_float(h01 & 0xFFFF0000u));
                const uint32_t l23 = pack_bf16(p2 - __uint_as_float(h23 << 16),
                                               p3 - __uint_as_float(h23 & 0xFFFF0000u));
                const uint32_t off = abase + row * APITCH + jq * 8;
                asm volatile("st.shared.v2.b32 [%0], {%1, %2};"
                             :: "r"(off), "r"(h01), "r"(h23) : "memory");
                asm volatile("st.shared.v2.b32 [%0], {%1, %2};"
                             :: "r"(off + A_HL), "r"(l01), "r"(l23) : "memory");
            }
            BAR_ARRIVE(FULL(slot));
        }

        // row sums: 8 lanes per row, reduce within each 8-lane group
#pragma unroll
        for (int ps = 0; ps < 4; ++ps) {
            float s = psum[ps];
            s += __shfl_xor_sync(0xffffffffu, s, 4);
            s += __shfl_xor_sync(0xffffffffu, s, 2);
            s += __shfl_xor_sync(0xffffffffu, s, 1);
            if ((lane & 7) == 0)
                ls[pw * 16 + ps * 4 + rsub] = s;
        }
    } else {
        // ================= CONSUMER =================
        const int cw = w - 8;            // 0..7
        const int mw = cw >> 1;          // 0..3 -> m base mw*32
        const int nw = cw & 1;           // 0..1 -> n base nw*32
        const int quad = lane >> 3, lr = lane & 7;
        const uint32_t aoff = (uint32_t)(((quad & 1) * 8 + lr) * APITCH
                                         + (quad >> 1) * 16);
        const uint32_t boff = (uint32_t)(((quad >> 1) * 8 + lr) * BPITCH
                                         + (quad & 1) * 16);
        const uint32_t aA0 = sbase + (mw * 32) * APITCH + aoff;
        const uint32_t aB0 = sbase + SB + (nw * 32) * BPITCH + boff;

        float acc[2][4][4];
#pragma unroll
        for (int i = 0; i < 2; ++i)
#pragma unroll
            for (int j = 0; j < 4; ++j)
#pragma unroll
                for (int k = 0; k < 4; ++k) acc[i][j][k] = 0.f;

#pragma unroll 1
        for (int t = 0; t < NT; ++t) {
            const int slot = t & 1;
            const int s = t >> 1;
            BAR_SYNC(FULL(slot));
            const uint32_t aAh = aA0 + slot * A_BUF;
            const uint32_t aAl = aAh + A_HL;
            const uint32_t aBh = aB0 + (s % 3) * B_BUF;
            const uint32_t aBl = aBh + B_HL;
            const uint32_t kb  = (t & 1) * 64;
#pragma unroll
            for (int kt = 0; kt < 2; ++kt) {
                const uint32_t koA = kt * 32;
                const uint32_t koB = kb + kt * 32;
                uint32_t ah0[4], ah1[4], bh0[4], bh1[4], bl0[4], bl1[4];
                uint32_t al0[4], al1[4];
                ldsm4(ah0, aAh + koA);
                ldsm4(ah1, aAh + 16 * APITCH + koA);
                ldsm4(bh0, aBh + koB);
                ldsm4(bh1, aBh + 16 * BPITCH + koB);
                // hh
                mma_bf16(acc[0][0], ah0, bh0[0], bh0[1]);
                mma_bf16(acc[0][1], ah0, bh0[2], bh0[3]);
                mma_bf16(acc[0][2], ah0, bh1[0], bh1[1]);
                mma_bf16(acc[0][3], ah0, bh1[2], bh1[3]);
                mma_bf16(acc[1][0], ah1, bh0[0], bh0[1]);
                mma_bf16(acc[1][1], ah1, bh0[2], bh0[3]);
                mma_bf16(acc[1][2], ah1, bh1[0], bh1[1]);
                mma_bf16(acc[1][3], ah1, bh1[2], bh1[3]);
                // hl
                ldsm4(bl0, aBl + koB);
                ldsm4(bl1, aBl + 16 * BPITCH + koB);
                mma_bf16(acc[0][0], ah0, bl0[0], bl0[1]);
                mma_bf16(acc[0][1], ah0, bl0[2], bl0[3]);
                mma_bf16(acc[0][2], ah0, bl1[0], bl1[1]);
                mma_bf16(acc[0][3], ah0, bl1[2], bl1[3]);
                mma_bf16(acc[1][0], ah1, bl0[0], bl0[1]);
                mma_bf16(acc[1][1], ah1, bl0[2], bl0[3]);
                mma_bf16(acc[1][2], ah1, bl1[0], bl1[1]);
                mma_bf16(acc[1][3], ah1, bl1[2], bl1[3]);
                // lh (ah dead -> al reuses its registers)
                ldsm4(al0, aAl + koA);
                ldsm4(al1, aAl + 16 * APITCH + koA);
                mma_bf16(acc[0][0], al0, bh0[0], bh0[1]);
                mma_bf16(acc[0][1], al0, bh0[2], bh0[3]);
                mma_bf16(acc[0][2], al0, bh1[0], bh1[1]);
                mma_bf16(acc[0][3], al0, bh1[2], bh1[3]);
                mma_bf16(acc[1][0], al1, bh0[0], bh0[1]);
                mma_bf16(acc[1][1], al1, bh0[2], bh0[3]);
                mma_bf16(acc[1][2], al1, bh1[0], bh1[1]);
                mma_bf16(acc[1][3], al1, bh1[2], bh1[3]);
            }
            BAR_ARRIVE(EMPTY(slot));
        }

        // epilogue deferred past the rejoin barrier (needs ls)
        __syncthreads();
        const size_t obase = (brow + i0) * F_OUT;
#pragma unroll
        for (int i = 0; i < 2; ++i) {
            const int r0 = mw * 32 + i * 16 + (lane >> 2);
            const float inv0 = 1.0f / ls[r0];
            const float inv1 = 1.0f / ls[r0 + 8];
#pragma unroll
            for (int j = 0; j < 4; ++j) {
                const int col = nw * 32 + j * 8 + 2 * (lane & 3);
                float x0 = acc[i][j][0] * inv0;
                float x1 = acc[i][j][1] * inv0;
                float x2 = acc[i][j][2] * inv1;
                float x3 = acc[i][j][3] * inv1;
                x0 = (x0 > 0.f) ? x0 : (expf(x0) - 1.f);
                x1 = (x1 > 0.f) ? x1 : (expf(x1) - 1.f);
                x2 = (x2 > 0.f) ? x2 : (expf(x2) - 1.f);
                x3 = (x3 > 0.f) ? x3 : (expf(x3) - 1.f);
                *(float2*)(out + obase + (size_t)r0 * F_OUT + col) =
                    make_float2(x0, x1);
                *(float2*)(out + obase + (size_t)(r0 + 8) * F_OUT + col) =
                    make_float2(x2, x3);
            }
        }
        return;
    }
    // producers rejoin the same barrier the consumers hit before their epilogue
    __syncthreads();
}

// ---------------------------------------------------------------------------
extern "C" void kernel_launch(void* const* d_in, const int* in_sizes, int n_in,
                              void* d_out, int out_size) {
    const float* h   = (const float*)d_in[0];
    const int*   adj = (const int*)d_in[1];
    const float* W   = (const float*)d_in[2];
    const float* a   = (const float*)d_in[3];
    float* out = (float*)d_out;
    (void)in_sizes; (void)n_in; (void)out_size;

    cudaFuncSetAttribute(k_wh, cudaFuncAttributeMaxDynamicSharedMemorySize,
                         WH_SMEM);
    cudaFuncSetAttribute(k_gat, cudaFuncAttributeMaxDynamicSharedMemorySize,
                         SMEM_TOTAL);

    k_wh<<<(B_DIM * M_DIM) / 64, 512, WH_SMEM>>>(h, W, a);

    dim3 grid2(M_DIM / BI, B_DIM);
    k_gat<<<grid2, 512, SMEM_TOTAL>>>(adj, out);
}